// round 1
// baseline (speedup 1.0000x reference)
#include <cuda_runtime.h>
#include <math.h>
#include <stdint.h>

#define D_MODEL 1024
#define NHEADS  16
#define HDIM    64
#define FFH     2048
#define BATCH   4
#define SEQ     2048
#define ROWS    (BATCH * SEQ)   // 8192

// ---------------- scratch (device globals; no allocation allowed) ----------
__device__ float g_h  [(size_t)ROWS * D_MODEL];     // LN output
__device__ float g_qkv[(size_t)ROWS * 3 * D_MODEL]; // fused QKV
__device__ float g_ctx[(size_t)ROWS * D_MODEL];     // attention context
__device__ float g_x2 [(size_t)ROWS * D_MODEL];     // x + attended
__device__ float g_ff [(size_t)ROWS * FFH];         // gelu(ff1)

// ---------------- LayerNorm: one block per row -----------------------------
__global__ void ln_kernel(const float* __restrict__ x,
                          const float* __restrict__ gw,
                          const float* __restrict__ gb,
                          float* __restrict__ out)
{
    __shared__ float red[2][8];
    int row = blockIdx.x;
    int t = threadIdx.x;                       // 256 threads, 4 floats each
    const float4* xr = (const float4*)(x + (size_t)row * D_MODEL);
    float4 v = xr[t];
    float s  = v.x + v.y + v.z + v.w;
    float ss = v.x*v.x + v.y*v.y + v.z*v.z + v.w*v.w;
    #pragma unroll
    for (int o = 16; o; o >>= 1) {
        s  += __shfl_xor_sync(0xffffffffu, s,  o);
        ss += __shfl_xor_sync(0xffffffffu, ss, o);
    }
    if ((t & 31) == 0) { red[0][t >> 5] = s; red[1][t >> 5] = ss; }
    __syncthreads();
    float ts = 0.f, tss = 0.f;
    #pragma unroll
    for (int i = 0; i < 8; ++i) { ts += red[0][i]; tss += red[1][i]; }
    float mu  = ts * (1.0f / D_MODEL);
    float var = tss * (1.0f / D_MODEL) - mu * mu;
    float inv = rsqrtf(var + 1e-5f);
    float4 g4 = ((const float4*)gw)[t];
    float4 b4 = ((const float4*)gb)[t];
    float4 o;
    o.x = (v.x - mu) * inv * g4.x + b4.x;
    o.y = (v.y - mu) * inv * g4.y + b4.y;
    o.z = (v.z - mu) * inv * g4.z + b4.z;
    o.w = (v.w - mu) * inv * g4.w + b4.w;
    ((float4*)(out + (size_t)row * D_MODEL))[t] = o;
}

// ---------------- SGEMM: 128x128 tile, BK=8, double-buffered ----------------
// MODE 0: C = A@B + bias
// MODE 1: C = A@B + bias + res
// MODE 2: C = gelu_exact(A@B + bias)
__device__ __forceinline__ float gelu_exact(float x) {
    return 0.5f * x * (1.0f + erff(x * 0.70710678118654752440f));
}

template<int MODE>
__global__ __launch_bounds__(256, 2)
void sgemm_kernel(const float* __restrict__ A, const float* __restrict__ B,
                  const float* __restrict__ bias, const float* __restrict__ res,
                  float* __restrict__ C, int M, int N, int K)
{
    __shared__ float As[2][8][128];   // transposed A tile: As[k][m]
    __shared__ float Bs[2][8][128];   // Bs[k][n]

    int t  = threadIdx.x;
    int tx = t & 15, ty = t >> 4;
    int bm = blockIdx.y << 7;
    int bn = blockIdx.x << 7;

    // loaders: one float4 each for A and B per K-tile
    int arow = t >> 1;            // 0..127
    int acol = (t & 1) << 2;      // 0 or 4
    int brow = t >> 5;            // 0..7
    int bcol = (t & 31) << 2;     // 0..124

    const float* Aptr = A + (size_t)(bm + arow) * K + acol;
    const float* Bptr = B + (size_t)brow * N + bn + bcol;

    float4 aReg = *(const float4*)Aptr;
    float4 bReg = *(const float4*)Bptr;

    As[0][acol + 0][arow] = aReg.x;
    As[0][acol + 1][arow] = aReg.y;
    As[0][acol + 2][arow] = aReg.z;
    As[0][acol + 3][arow] = aReg.w;
    *(float4*)&Bs[0][brow][bcol] = bReg;
    __syncthreads();

    float acc[8][8];
    #pragma unroll
    for (int i = 0; i < 8; ++i)
        #pragma unroll
        for (int j = 0; j < 8; ++j) acc[i][j] = 0.f;

    int nk = K >> 3;
    for (int kt = 0; kt < nk; ++kt) {
        int buf = kt & 1;
        bool has = (kt + 1) < nk;
        float4 an, bn2;
        if (has) {
            an  = *(const float4*)(Aptr + (kt + 1) * 8);
            bn2 = *(const float4*)(Bptr + (size_t)(kt + 1) * 8 * N);
        }
        #pragma unroll
        for (int kk = 0; kk < 8; ++kk) {
            float4 a0 = *(const float4*)&As[buf][kk][(ty << 2)];
            float4 a1 = *(const float4*)&As[buf][kk][(ty << 2) + 64];
            float4 b0 = *(const float4*)&Bs[buf][kk][(tx << 2)];
            float4 b1 = *(const float4*)&Bs[buf][kk][(tx << 2) + 64];
            float av[8] = {a0.x,a0.y,a0.z,a0.w,a1.x,a1.y,a1.z,a1.w};
            float bv[8] = {b0.x,b0.y,b0.z,b0.w,b1.x,b1.y,b1.z,b1.w};
            #pragma unroll
            for (int i = 0; i < 8; ++i)
                #pragma unroll
                for (int j = 0; j < 8; ++j)
                    acc[i][j] = fmaf(av[i], bv[j], acc[i][j]);
        }
        if (has) {
            int nb = buf ^ 1;
            As[nb][acol + 0][arow] = an.x;
            As[nb][acol + 1][arow] = an.y;
            As[nb][acol + 2][arow] = an.z;
            As[nb][acol + 3][arow] = an.w;
            *(float4*)&Bs[nb][brow][bcol] = bn2;
            __syncthreads();
        }
    }

    // epilogue
    #pragma unroll
    for (int ih = 0; ih < 2; ++ih) {
        #pragma unroll
        for (int i = 0; i < 4; ++i) {
            size_t r = (size_t)(bm + (ty << 2) + i + ih * 64);
            #pragma unroll
            for (int jh = 0; jh < 2; ++jh) {
                int c = bn + (tx << 2) + jh * 64;
                float4 bia = *(const float4*)(bias + c);
                float4 o;
                o.x = acc[ih * 4 + i][jh * 4 + 0] + bia.x;
                o.y = acc[ih * 4 + i][jh * 4 + 1] + bia.y;
                o.z = acc[ih * 4 + i][jh * 4 + 2] + bia.z;
                o.w = acc[ih * 4 + i][jh * 4 + 3] + bia.w;
                if (MODE == 1) {
                    float4 rr = *(const float4*)(res + r * N + c);
                    o.x += rr.x; o.y += rr.y; o.z += rr.z; o.w += rr.w;
                }
                if (MODE == 2) {
                    o.x = gelu_exact(o.x); o.y = gelu_exact(o.y);
                    o.z = gelu_exact(o.z); o.w = gelu_exact(o.w);
                }
                *(float4*)(C + r * N + c) = o;
            }
        }
    }
}

// ---------------- Flash attention, fp32 -------------------------------------
// Q/K/V read from fused qkv buffer [B, L, 3*D], row stride 3072.
// Per block: 64 q-rows x one (b,h); KV tiles of 32. Writes ctx in [B, L, D].
__global__ __launch_bounds__(256)
void attn_kernel(const float* __restrict__ qkv, float* __restrict__ ctx)
{
    __shared__ float Qs[64][68];
    __shared__ float Ks[32][68];
    __shared__ float Vs[32][68];
    __shared__ float Ps[64][36];

    int t  = threadIdx.x;
    int tx = t & 15, ty = t >> 4;
    int bh = blockIdx.y;
    int b  = bh >> 4, h = bh & 15;
    int q0 = blockIdx.x << 6;

    const float* qbase = qkv + (size_t)b * SEQ * (3 * D_MODEL) + h * HDIM;

    int lr = t >> 4;          // 0..15
    int lc = (t & 15) << 2;   // 0..60

    // load Q tile, pre-scaled by 1/sqrt(Dh) = 0.125
    #pragma unroll
    for (int rr = 0; rr < 4; ++rr) {
        int r = lr + (rr << 4);
        float4 v = *(const float4*)(qbase + (size_t)(q0 + r) * (3 * D_MODEL) + lc);
        Qs[r][lc + 0] = v.x * 0.125f;
        Qs[r][lc + 1] = v.y * 0.125f;
        Qs[r][lc + 2] = v.z * 0.125f;
        Qs[r][lc + 3] = v.w * 0.125f;
    }

    float m[4], l[4], acc[4][4];
    #pragma unroll
    for (int i = 0; i < 4; ++i) {
        m[i] = -1e30f; l[i] = 0.f;
        #pragma unroll
        for (int j = 0; j < 4; ++j) acc[i][j] = 0.f;
    }

    for (int kt = 0; kt < SEQ / 32; ++kt) {
        __syncthreads();   // protect Ks/Vs/Ps from previous iteration readers
        #pragma unroll
        for (int rr = 0; rr < 2; ++rr) {
            int r = lr + (rr << 4);
            const float* kp = qbase + D_MODEL + (size_t)(kt * 32 + r) * (3 * D_MODEL) + lc;
            float4 kv = *(const float4*)kp;
            float4 vv = *(const float4*)(kp + D_MODEL);
            Ks[r][lc + 0] = kv.x; Ks[r][lc + 1] = kv.y;
            Ks[r][lc + 2] = kv.z; Ks[r][lc + 3] = kv.w;
            Vs[r][lc + 0] = vv.x; Vs[r][lc + 1] = vv.y;
            Vs[r][lc + 2] = vv.z; Vs[r][lc + 3] = vv.w;
        }
        __syncthreads();

        // S = Q @ K^T  (thread: rows ty*4+i, cols tx*2+j)
        float s[4][2] = {{0,0},{0,0},{0,0},{0,0}};
        #pragma unroll
        for (int d4 = 0; d4 < 16; ++d4) {
            int d = d4 << 2;
            float4 b0 = *(const float4*)&Ks[(tx << 1) + 0][d];
            float4 b1 = *(const float4*)&Ks[(tx << 1) + 1][d];
            #pragma unroll
            for (int i = 0; i < 4; ++i) {
                float4 a = *(const float4*)&Qs[(ty << 2) + i][d];
                s[i][0] = fmaf(a.x, b0.x, fmaf(a.y, b0.y, fmaf(a.z, b0.z, fmaf(a.w, b0.w, s[i][0]))));
                s[i][1] = fmaf(a.x, b1.x, fmaf(a.y, b1.y, fmaf(a.z, b1.z, fmaf(a.w, b1.w, s[i][1]))));
            }
        }

        // online softmax over each row (16 lanes per row-group)
        #pragma unroll
        for (int i = 0; i < 4; ++i) {
            float rmax = fmaxf(s[i][0], s[i][1]);
            #pragma unroll
            for (int o = 8; o; o >>= 1)
                rmax = fmaxf(rmax, __shfl_xor_sync(0xffffffffu, rmax, o, 16));
            float mnew  = fmaxf(m[i], rmax);
            float alpha = __expf(m[i] - mnew);
            float p0 = __expf(s[i][0] - mnew);
            float p1 = __expf(s[i][1] - mnew);
            float rsum = p0 + p1;
            #pragma unroll
            for (int o = 8; o; o >>= 1)
                rsum += __shfl_xor_sync(0xffffffffu, rsum, o, 16);
            l[i] = l[i] * alpha + rsum;
            m[i] = mnew;
            Ps[(ty << 2) + i][(tx << 1) + 0] = p0;
            Ps[(ty << 2) + i][(tx << 1) + 1] = p1;
            #pragma unroll
            for (int j = 0; j < 4; ++j) acc[i][j] *= alpha;
        }
        __syncthreads();

        // O += P @ V  (thread: rows ty*4+i, d-cols tx*4+j)
        #pragma unroll
        for (int c4 = 0; c4 < 8; ++c4) {
            float pr[4][4];
            #pragma unroll
            for (int i = 0; i < 4; ++i) {
                float4 pv = *(const float4*)&Ps[(ty << 2) + i][c4 << 2];
                pr[i][0] = pv.x; pr[i][1] = pv.y; pr[i][2] = pv.z; pr[i][3] = pv.w;
            }
            #pragma unroll
            for (int cc = 0; cc < 4; ++cc) {
                float4 v4 = *(const float4*)&Vs[(c4 << 2) + cc][tx << 2];
                #pragma unroll
                for (int i = 0; i < 4; ++i) {
                    acc[i][0] = fmaf(pr[i][cc], v4.x, acc[i][0]);
                    acc[i][1] = fmaf(pr[i][cc], v4.y, acc[i][1]);
                    acc[i][2] = fmaf(pr[i][cc], v4.z, acc[i][2]);
                    acc[i][3] = fmaf(pr[i][cc], v4.w, acc[i][3]);
                }
            }
        }
    }

    // finalize + write ctx in [B, L, D] layout
    #pragma unroll
    for (int i = 0; i < 4; ++i) {
        float inv = 1.0f / l[i];
        size_t row = (size_t)b * SEQ + q0 + (ty << 2) + i;
        float4 o;
        o.x = acc[i][0] * inv; o.y = acc[i][1] * inv;
        o.z = acc[i][2] * inv; o.w = acc[i][3] * inv;
        *(float4*)(ctx + row * D_MODEL + h * HDIM + (tx << 2)) = o;
    }
}

// ---------------- launch ----------------------------------------------------
extern "C" void kernel_launch(void* const* d_in, const int* in_sizes, int n_in,
                              void* d_out, int out_size)
{
    const float* x     = (const float*)d_in[0];
    const float* qkv_w = (const float*)d_in[1];
    const float* qkv_b = (const float*)d_in[2];
    const float* out_w = (const float*)d_in[3];
    const float* out_b = (const float*)d_in[4];
    const float* ff1_w = (const float*)d_in[5];
    const float* ff1_b = (const float*)d_in[6];
    const float* ff2_w = (const float*)d_in[7];
    const float* ff2_b = (const float*)d_in[8];
    const float* ln1_g = (const float*)d_in[9];
    const float* ln1_b = (const float*)d_in[10];
    const float* ln2_g = (const float*)d_in[11];
    const float* ln2_b = (const float*)d_in[12];
    float* out = (float*)d_out;

    void *ph, *pqkv, *pctx, *px2, *pff;
    cudaGetSymbolAddress(&ph,   g_h);
    cudaGetSymbolAddress(&pqkv, g_qkv);
    cudaGetSymbolAddress(&pctx, g_ctx);
    cudaGetSymbolAddress(&px2,  g_x2);
    cudaGetSymbolAddress(&pff,  g_ff);
    float* hbuf   = (float*)ph;
    float* qkvbuf = (float*)pqkv;
    float* ctxbuf = (float*)pctx;
    float* x2buf  = (float*)px2;
    float* ffbuf  = (float*)pff;

    // 1) h = LN1(x)
    ln_kernel<<<ROWS, 256>>>(x, ln1_g, ln1_b, hbuf);
    // 2) qkv = h @ qkv_w + qkv_b
    sgemm_kernel<0><<<dim3(3 * D_MODEL / 128, ROWS / 128), 256>>>(
        hbuf, qkv_w, qkv_b, nullptr, qkvbuf, ROWS, 3 * D_MODEL, D_MODEL);
    // 3) ctx = attention(q, k, v)
    attn_kernel<<<dim3(SEQ / 64, BATCH * NHEADS), 256>>>(qkvbuf, ctxbuf);
    // 4) x2 = x + ctx @ out_w + out_b
    sgemm_kernel<1><<<dim3(D_MODEL / 128, ROWS / 128), 256>>>(
        ctxbuf, out_w, out_b, x, x2buf, ROWS, D_MODEL, D_MODEL);
    // 5) h = LN2(x2)
    ln_kernel<<<ROWS, 256>>>(x2buf, ln2_g, ln2_b, hbuf);
    // 6) ff = gelu(h @ ff1_w + ff1_b)
    sgemm_kernel<2><<<dim3(FFH / 128, ROWS / 128), 256>>>(
        hbuf, ff1_w, ff1_b, nullptr, ffbuf, ROWS, FFH, D_MODEL);
    // 7) out = x2 + ff @ ff2_w + ff2_b
    sgemm_kernel<1><<<dim3(D_MODEL / 128, ROWS / 128), 256>>>(
        ffbuf, ff2_w, ff2_b, x2buf, out, ROWS, D_MODEL, FFH);
}

// round 4
// speedup vs baseline: 1.5508x; 1.5508x over previous
#include <cuda_runtime.h>
#include <math.h>
#include <stdint.h>

#define D_MODEL 1024
#define NHEADS  16
#define HDIM    64
#define FFH     2048
#define BATCH   4
#define SEQ     2048
#define ROWS    (BATCH * SEQ)   // 8192

// ---------------- scratch (device globals; no allocation allowed) ----------
__device__ float g_h  [(size_t)ROWS * D_MODEL];
__device__ float g_qkv[(size_t)ROWS * 3 * D_MODEL];
__device__ float g_ctx[(size_t)ROWS * D_MODEL];
__device__ float g_x2 [(size_t)ROWS * D_MODEL];
__device__ float g_ff [(size_t)ROWS * FFH];
__device__ float g_wR [8388608];          // tf32-rounded weights, original [K][N] layout
#define WT_QKV 0
#define WT_OUT 3145728
#define WT_FF1 4194304
#define WT_FF2 6291456

// ============================ helpers =======================================
__device__ __forceinline__ uint32_t smem_u32(const void* p) {
    uint32_t a;
    asm("{ .reg .u64 t; cvta.to.shared.u64 t, %1; cvt.u32.u64 %0, t; }"
        : "=r"(a) : "l"(p));
    return a;
}
__device__ __forceinline__ float rtf32(float x) {
    uint32_t r;
    asm("cvt.rna.tf32.f32 %0, %1;" : "=r"(r) : "f"(x));
    return __uint_as_float(r);
}
__device__ __forceinline__ float gelu_exact(float x) {
    return 0.5f * x * (1.0f + erff(x * 0.70710678118654752440f));
}

#define CPA16(s, g) asm volatile("cp.async.cg.shared.global [%0], [%1], 16;\n" :: "r"(s), "l"(g))
#define CPC()       asm volatile("cp.async.commit_group;\n")
#define CPW(n)      asm volatile("cp.async.wait_group %0;\n" :: "n"(n))

#define MMA_TF32(c, a, b) \
    asm volatile("mma.sync.aligned.m16n8k8.row.col.f32.tf32.tf32.f32 " \
        "{%0,%1,%2,%3}, {%4,%5,%6,%7}, {%8,%9}, {%0,%1,%2,%3};" \
        : "+f"((c)[0]), "+f"((c)[1]), "+f"((c)[2]), "+f"((c)[3]) \
        : "r"((a)[0]), "r"((a)[1]), "r"((a)[2]), "r"((a)[3]), \
          "r"((b)[0]), "r"((b)[1]))

// ============================ TF32 mma.sync GEMM ============================
// C[M,N] = A[M,K] @ B[K,N], A/B pre-rounded to tf32.
// MODE 0: +bias   MODE 1: +bias+res   MODE 2: gelu(+bias), output tf32-rounded
#define BM 128
#define BN 128
#define BK 32
#define ALD 36                 // A smem lead (floats)
#define BLD 136                // B smem lead (floats)
#define ASZF (BM * ALD)        // 4608 floats
#define BSZF (BK * BLD)        // 4352 floats
#define STGF (ASZF + BSZF)     // 8960 floats = 35840 B
#define GEMM_SMEM (3 * STGF * 4)

__device__ __forceinline__ void ld_stage(uint32_t sA, uint32_t sB,
                                         const float* A, const float* B,
                                         int bm, int bn, int kc, int K, int N, int t)
{
    #pragma unroll
    for (int i = 0; i < 4; ++i) {                 // A: 128 rows x 8 x 16B
        int idx = t + (i << 8);
        int row = idx >> 3, u = idx & 7;
        CPA16(sA + (uint32_t)(row * ALD + u * 4) * 4,
              A + (size_t)(bm + row) * K + kc + u * 4);
    }
    #pragma unroll
    for (int i = 0; i < 4; ++i) {                 // B: 32 rows x 32 x 16B
        int idx = t + (i << 8);
        int row = idx >> 5, u = idx & 31;
        CPA16(sB + (uint32_t)(row * BLD + u * 4) * 4,
              B + (size_t)(kc + row) * N + bn + u * 4);
    }
}

template<int MODE>
__global__ __launch_bounds__(256)
void mma_gemm(const float* __restrict__ A, const float* __restrict__ B,
              const float* __restrict__ bias, const float* __restrict__ res,
              float* __restrict__ C, int K, int N)
{
    extern __shared__ float sm[];
    uint32_t sbase = smem_u32(sm);
    int t = threadIdx.x, lane = t & 31, wid = t >> 5;
    int wm = wid & 1, wn = wid >> 1;              // warp tile: 64 (M) x 32 (N)
    int bm = blockIdx.y * BM, bn = blockIdx.x * BN;
    int lr = lane >> 2, lc = lane & 3;

    float acc[4][4][4];
    #pragma unroll
    for (int i = 0; i < 4; ++i)
        #pragma unroll
        for (int j = 0; j < 4; ++j)
            #pragma unroll
            for (int v = 0; v < 4; ++v) acc[i][j][v] = 0.f;

    int NK = K / BK;
    ld_stage(sbase, sbase + ASZF * 4, A, B, bm, bn, 0, K, N, t); CPC();
    ld_stage(sbase + STGF * 4, sbase + (STGF + ASZF) * 4, A, B, bm, bn, BK, K, N, t); CPC();

    for (int c = 0; c < NK; ++c) {
        CPW(1);
        __syncthreads();
        if (c + 2 < NK) {
            int s2 = (c + 2) % 3;
            ld_stage(sbase + (uint32_t)s2 * STGF * 4,
                     sbase + ((uint32_t)s2 * STGF + ASZF) * 4,
                     A, B, bm, bn, (c + 2) * BK, K, N, t);
        }
        CPC();

        const float* As = sm + (c % 3) * STGF;
        const float* Bs = As + ASZF;
        #pragma unroll
        for (int ks = 0; ks < 4; ++ks) {
            int k0 = ks << 3;
            uint32_t af[4][4], bf[4][2];
            #pragma unroll
            for (int mi = 0; mi < 4; ++mi) {
                int row = wm * 64 + mi * 16 + lr;
                int col = k0 + lc;
                af[mi][0] = __float_as_uint(As[row * ALD + col]);
                af[mi][1] = __float_as_uint(As[(row + 8) * ALD + col]);
                af[mi][2] = __float_as_uint(As[row * ALD + col + 4]);
                af[mi][3] = __float_as_uint(As[(row + 8) * ALD + col + 4]);
            }
            #pragma unroll
            for (int ni = 0; ni < 4; ++ni) {
                int n = wn * 32 + ni * 8 + lr;
                bf[ni][0] = __float_as_uint(Bs[(k0 + lc) * BLD + n]);
                bf[ni][1] = __float_as_uint(Bs[(k0 + 4 + lc) * BLD + n]);
            }
            #pragma unroll
            for (int mi = 0; mi < 4; ++mi)
                #pragma unroll
                for (int ni = 0; ni < 4; ++ni)
                    MMA_TF32(acc[mi][ni], af[mi], bf[ni]);
        }
    }
    CPW(0);

    // epilogue: c0,c1 -> (row, col..col+1); c2,c3 -> (row+8, ...)
    #pragma unroll
    for (int mi = 0; mi < 4; ++mi) {
        int row0 = bm + wm * 64 + mi * 16 + lr;
        #pragma unroll
        for (int ni = 0; ni < 4; ++ni) {
            int col = bn + wn * 32 + ni * 8 + (lc << 1);
            #pragma unroll
            for (int hl = 0; hl < 2; ++hl) {
                size_t r = (size_t)(row0 + hl * 8);
                float v0 = acc[mi][ni][hl * 2 + 0] + bias[col];
                float v1 = acc[mi][ni][hl * 2 + 1] + bias[col + 1];
                if (MODE == 1) {
                    v0 += res[r * N + col];
                    v1 += res[r * N + col + 1];
                }
                if (MODE == 2) {
                    v0 = rtf32(gelu_exact(v0));
                    v1 = rtf32(gelu_exact(v1));
                }
                float2 o = make_float2(v0, v1);
                *(float2*)(C + r * N + col) = o;
            }
        }
    }
}

// ---------------- round-copy (weights -> tf32) -------------------------------
__global__ void round_copy(const float* __restrict__ in, float* __restrict__ out, int n4)
{
    int i = blockIdx.x * blockDim.x + threadIdx.x;
    if (i < n4) {
        float4 v = ((const float4*)in)[i];
        v.x = rtf32(v.x); v.y = rtf32(v.y); v.z = rtf32(v.z); v.w = rtf32(v.w);
        ((float4*)out)[i] = v;
    }
}

// ---------------- LayerNorm (output tf32-rounded) ----------------------------
__global__ void ln_kernel(const float* __restrict__ x,
                          const float* __restrict__ gw,
                          const float* __restrict__ gb,
                          float* __restrict__ out)
{
    __shared__ float red[2][8];
    int row = blockIdx.x;
    int t = threadIdx.x;
    const float4* xr = (const float4*)(x + (size_t)row * D_MODEL);
    float4 v = xr[t];
    float s  = v.x + v.y + v.z + v.w;
    float ss = v.x*v.x + v.y*v.y + v.z*v.z + v.w*v.w;
    #pragma unroll
    for (int o = 16; o; o >>= 1) {
        s  += __shfl_xor_sync(0xffffffffu, s,  o);
        ss += __shfl_xor_sync(0xffffffffu, ss, o);
    }
    if ((t & 31) == 0) { red[0][t >> 5] = s; red[1][t >> 5] = ss; }
    __syncthreads();
    float ts = 0.f, tss = 0.f;
    #pragma unroll
    for (int i = 0; i < 8; ++i) { ts += red[0][i]; tss += red[1][i]; }
    float mu  = ts * (1.0f / D_MODEL);
    float var = tss * (1.0f / D_MODEL) - mu * mu;
    float inv = rsqrtf(var + 1e-5f);
    float4 g4 = ((const float4*)gw)[t];
    float4 b4 = ((const float4*)gb)[t];
    float4 o;
    o.x = rtf32((v.x - mu) * inv * g4.x + b4.x);
    o.y = rtf32((v.y - mu) * inv * g4.y + b4.y);
    o.z = rtf32((v.z - mu) * inv * g4.z + b4.z);
    o.w = rtf32((v.w - mu) * inv * g4.w + b4.w);
    ((float4*)(out + (size_t)row * D_MODEL))[t] = o;
}

// ---------------- Flash attention, fp32 (ctx output tf32-rounded) ------------
__global__ __launch_bounds__(256)
void attn_kernel(const float* __restrict__ qkv, float* __restrict__ ctx)
{
    __shared__ float Qs[64][68];
    __shared__ float Ks[32][68];
    __shared__ float Vs[32][68];
    __shared__ float Ps[64][36];

    int t  = threadIdx.x;
    int tx = t & 15, ty = t >> 4;
    int bh = blockIdx.y;
    int b  = bh >> 4, h = bh & 15;
    int q0 = blockIdx.x << 6;

    const float* qbase = qkv + (size_t)b * SEQ * (3 * D_MODEL) + h * HDIM;

    int lr = t >> 4;
    int lc = (t & 15) << 2;

    #pragma unroll
    for (int rr = 0; rr < 4; ++rr) {
        int r = lr + (rr << 4);
        float4 v = *(const float4*)(qbase + (size_t)(q0 + r) * (3 * D_MODEL) + lc);
        Qs[r][lc + 0] = v.x * 0.125f;
        Qs[r][lc + 1] = v.y * 0.125f;
        Qs[r][lc + 2] = v.z * 0.125f;
        Qs[r][lc + 3] = v.w * 0.125f;
    }

    float m[4], l[4], acc[4][4];
    #pragma unroll
    for (int i = 0; i < 4; ++i) {
        m[i] = -1e30f; l[i] = 0.f;
        #pragma unroll
        for (int j = 0; j < 4; ++j) acc[i][j] = 0.f;
    }

    for (int kt = 0; kt < SEQ / 32; ++kt) {
        __syncthreads();
        #pragma unroll
        for (int rr = 0; rr < 2; ++rr) {
            int r = lr + (rr << 4);
            const float* kp = qbase + D_MODEL + (size_t)(kt * 32 + r) * (3 * D_MODEL) + lc;
            float4 kv = *(const float4*)kp;
            float4 vv = *(const float4*)(kp + D_MODEL);
            Ks[r][lc + 0] = kv.x; Ks[r][lc + 1] = kv.y;
            Ks[r][lc + 2] = kv.z; Ks[r][lc + 3] = kv.w;
            Vs[r][lc + 0] = vv.x; Vs[r][lc + 1] = vv.y;
            Vs[r][lc + 2] = vv.z; Vs[r][lc + 3] = vv.w;
        }
        __syncthreads();

        float s[4][2] = {{0,0},{0,0},{0,0},{0,0}};
        #pragma unroll
        for (int d4 = 0; d4 < 16; ++d4) {
            int d = d4 << 2;
            float4 b0 = *(const float4*)&Ks[(tx << 1) + 0][d];
            float4 b1 = *(const float4*)&Ks[(tx << 1) + 1][d];
            #pragma unroll
            for (int i = 0; i < 4; ++i) {
                float4 a = *(const float4*)&Qs[(ty << 2) + i][d];
                s[i][0] = fmaf(a.x, b0.x, fmaf(a.y, b0.y, fmaf(a.z, b0.z, fmaf(a.w, b0.w, s[i][0]))));
                s[i][1] = fmaf(a.x, b1.x, fmaf(a.y, b1.y, fmaf(a.z, b1.z, fmaf(a.w, b1.w, s[i][1]))));
            }
        }

        #pragma unroll
        for (int i = 0; i < 4; ++i) {
            float rmax = fmaxf(s[i][0], s[i][1]);
            #pragma unroll
            for (int o = 8; o; o >>= 1)
                rmax = fmaxf(rmax, __shfl_xor_sync(0xffffffffu, rmax, o, 16));
            float mnew  = fmaxf(m[i], rmax);
            float alpha = __expf(m[i] - mnew);
            float p0 = __expf(s[i][0] - mnew);
            float p1 = __expf(s[i][1] - mnew);
            float rsum = p0 + p1;
            #pragma unroll
            for (int o = 8; o; o >>= 1)
                rsum += __shfl_xor_sync(0xffffffffu, rsum, o, 16);
            l[i] = l[i] * alpha + rsum;
            m[i] = mnew;
            Ps[(ty << 2) + i][(tx << 1) + 0] = p0;
            Ps[(ty << 2) + i][(tx << 1) + 1] = p1;
            #pragma unroll
            for (int j = 0; j < 4; ++j) acc[i][j] *= alpha;
        }
        __syncthreads();

        #pragma unroll
        for (int c4 = 0; c4 < 8; ++c4) {
            float pr[4][4];
            #pragma unroll
            for (int i = 0; i < 4; ++i) {
                float4 pv = *(const float4*)&Ps[(ty << 2) + i][c4 << 2];
                pr[i][0] = pv.x; pr[i][1] = pv.y; pr[i][2] = pv.z; pr[i][3] = pv.w;
            }
            #pragma unroll
            for (int cc = 0; cc < 4; ++cc) {
                float4 v4 = *(const float4*)&Vs[(c4 << 2) + cc][tx << 2];
                #pragma unroll
                for (int i = 0; i < 4; ++i) {
                    acc[i][0] = fmaf(pr[i][cc], v4.x, acc[i][0]);
                    acc[i][1] = fmaf(pr[i][cc], v4.y, acc[i][1]);
                    acc[i][2] = fmaf(pr[i][cc], v4.z, acc[i][2]);
                    acc[i][3] = fmaf(pr[i][cc], v4.w, acc[i][3]);
                }
            }
        }
    }

    #pragma unroll
    for (int i = 0; i < 4; ++i) {
        float inv = 1.0f / l[i];
        size_t row = (size_t)b * SEQ + q0 + (ty << 2) + i;
        float4 o;
        o.x = rtf32(acc[i][0] * inv); o.y = rtf32(acc[i][1] * inv);
        o.z = rtf32(acc[i][2] * inv); o.w = rtf32(acc[i][3] * inv);
        *(float4*)(ctx + row * D_MODEL + h * HDIM + (tx << 2)) = o;
    }
}

// ---------------- launch -----------------------------------------------------
extern "C" void kernel_launch(void* const* d_in, const int* in_sizes, int n_in,
                              void* d_out, int out_size)
{
    const float* x     = (const float*)d_in[0];
    const float* qkv_w = (const float*)d_in[1];
    const float* qkv_b = (const float*)d_in[2];
    const float* out_w = (const float*)d_in[3];
    const float* out_b = (const float*)d_in[4];
    const float* ff1_w = (const float*)d_in[5];
    const float* ff1_b = (const float*)d_in[6];
    const float* ff2_w = (const float*)d_in[7];
    const float* ff2_b = (const float*)d_in[8];
    const float* ln1_g = (const float*)d_in[9];
    const float* ln1_b = (const float*)d_in[10];
    const float* ln2_g = (const float*)d_in[11];
    const float* ln2_b = (const float*)d_in[12];
    float* out = (float*)d_out;

    void *ph, *pqkv, *pctx, *px2, *pff, *pw;
    cudaGetSymbolAddress(&ph,   g_h);
    cudaGetSymbolAddress(&pqkv, g_qkv);
    cudaGetSymbolAddress(&pctx, g_ctx);
    cudaGetSymbolAddress(&px2,  g_x2);
    cudaGetSymbolAddress(&pff,  g_ff);
    cudaGetSymbolAddress(&pw,   g_wR);
    float* hbuf   = (float*)ph;
    float* qkvbuf = (float*)pqkv;
    float* ctxbuf = (float*)pctx;
    float* x2buf  = (float*)px2;
    float* ffbuf  = (float*)pff;
    float* wR     = (float*)pw;

    cudaFuncSetAttribute(mma_gemm<0>, cudaFuncAttributeMaxDynamicSharedMemorySize, GEMM_SMEM);
    cudaFuncSetAttribute(mma_gemm<1>, cudaFuncAttributeMaxDynamicSharedMemorySize, GEMM_SMEM);
    cudaFuncSetAttribute(mma_gemm<2>, cudaFuncAttributeMaxDynamicSharedMemorySize, GEMM_SMEM);

    // weights -> tf32-rounded copies (same [K][N] layout)
    round_copy<<<(3145728/4 + 255)/256, 256>>>(qkv_w, wR + WT_QKV, 3145728/4);
    round_copy<<<(1048576/4 + 255)/256, 256>>>(out_w, wR + WT_OUT, 1048576/4);
    round_copy<<<(2097152/4 + 255)/256, 256>>>(ff1_w, wR + WT_FF1, 2097152/4);
    round_copy<<<(2097152/4 + 255)/256, 256>>>(ff2_w, wR + WT_FF2, 2097152/4);

    // 1) h = LN1(x)   (tf32-rounded)
    ln_kernel<<<ROWS, 256>>>(x, ln1_g, ln1_b, hbuf);
    // 2) qkv = h @ qkv_w + qkv_b
    mma_gemm<0><<<dim3(3 * D_MODEL / BN, ROWS / BM), 256, GEMM_SMEM>>>(
        hbuf, wR + WT_QKV, qkv_b, nullptr, qkvbuf, D_MODEL, 3 * D_MODEL);
    // 3) ctx = attention
    attn_kernel<<<dim3(SEQ / 64, BATCH * NHEADS), 256>>>(qkvbuf, ctxbuf);
    // 4) x2 = x + ctx @ out_w + out_b
    mma_gemm<1><<<dim3(D_MODEL / BN, ROWS / BM), 256, GEMM_SMEM>>>(
        ctxbuf, wR + WT_OUT, out_b, x, x2buf, D_MODEL, D_MODEL);
    // 5) h = LN2(x2)
    ln_kernel<<<ROWS, 256>>>(x2buf, ln2_g, ln2_b, hbuf);
    // 6) ff = gelu(h @ ff1_w + ff1_b)   (tf32-rounded output)
    mma_gemm<2><<<dim3(FFH / BN, ROWS / BM), 256, GEMM_SMEM>>>(
        hbuf, wR + WT_FF1, ff1_b, nullptr, ffbuf, D_MODEL, FFH);
    // 7) out = x2 + ff @ ff2_w + ff2_b
    mma_gemm<1><<<dim3(D_MODEL / BN, ROWS / BM), 256, GEMM_SMEM>>>(
        ffbuf, wR + WT_FF2, ff2_b, x2buf, out, FFH, D_MODEL);
}